// round 1
// baseline (speedup 1.0000x reference)
#include <cuda_runtime.h>
#include <cuda_bf16.h>
#include <math.h>

#define N_NODES 100000
#define N_FEAT  100
#define HID     32
#define N_EDGES 1600000

// Scratch (static device globals — no allocations allowed)
__device__ float g_x    [N_NODES * HID];  // relu(lin1)
__device__ float g_xn   [N_NODES * HID];  // row-normalized
__device__ float g_acc  [N_NODES * HID];  // unnormalized weighted aggregate
__device__ float g_denom[N_NODES];        // sum of exp(alpha)

// ---------------------------------------------------------------------------
// K1: x = relu(X @ W1^T + b1); xn = x/||x||; init acc/denom with self-loop.
// One warp per node, lane = hidden unit. W1 (32x100 = 12.8KB) staged in smem.
// ---------------------------------------------------------------------------
__global__ void __launch_bounds__(256) k1_lin1_norm(
    const float* __restrict__ X,
    const float* __restrict__ W1,
    const float* __restrict__ b1,
    const float* __restrict__ beta_p)
{
    __shared__ float sW[HID * N_FEAT];
    int tid = threadIdx.x;
    for (int i = tid; i < HID * N_FEAT; i += blockDim.x) sW[i] = W1[i];
    __syncthreads();

    int lane = tid & 31;
    int node = blockIdx.x * (blockDim.x >> 5) + (tid >> 5);
    if (node >= N_NODES) return;

    const float* xr = X + (size_t)node * N_FEAT;   // broadcast reads within warp
    const float* wr = sW + lane * N_FEAT;          // conflict-free (same bank phase per iter? stride 100*4B: lane*400B -> bank (lane*100)%32 = lane*4 %32 -> 8-way conflict worst-case, acceptable)

    float acc = b1[lane];
    #pragma unroll 4
    for (int k = 0; k < N_FEAT; k++) acc = fmaf(xr[k], wr[k], acc);
    float v = fmaxf(acc, 0.0f);

    // row norm across 32 lanes
    float s = v * v;
    #pragma unroll
    for (int o = 16; o > 0; o >>= 1) s += __shfl_xor_sync(0xffffffffu, s, o);
    float nrm = fmaxf(sqrtf(s), 1e-12f);
    float xn  = v / nrm;

    int idx = node * HID + lane;
    g_x [idx] = v;
    g_xn[idx] = xn;

    // self-loop: alpha = beta * <xn, xn>
    float d = xn * xn;
    #pragma unroll
    for (int o = 16; o > 0; o >>= 1) d += __shfl_xor_sync(0xffffffffu, d, o);
    float w = expf((*beta_p) * d);

    g_acc[idx] = w * v;                 // initializes acc (no memset needed)
    if (lane == 0) g_denom[node] = w;   // initializes denom
}

// ---------------------------------------------------------------------------
// K2: per-edge attention + scatter. One warp per edge.
//   alpha = beta * <xn[tgt], xn[src]>;  w = exp(alpha)   (max-shift not needed:
//   alpha in [-|beta|, |beta|], bounded — softmax is shift-invariant)
//   denom[tgt] += w;  acc[tgt] += w * x[src]
// ---------------------------------------------------------------------------
__global__ void __launch_bounds__(256) k2_edges(
    const int* __restrict__ esrc,
    const int* __restrict__ etgt,
    const float* __restrict__ beta_p)
{
    int lane = threadIdx.x & 31;
    int e = blockIdx.x * (blockDim.x >> 5) + (threadIdx.x >> 5);
    if (e >= N_EDGES) return;

    int s = esrc[e];   // uniform within warp -> broadcast
    int t = etgt[e];

    float xs = g_xn[s * HID + lane];
    float xt = g_xn[t * HID + lane];
    float d  = xs * xt;
    #pragma unroll
    for (int o = 16; o > 0; o >>= 1) d += __shfl_xor_sync(0xffffffffu, d, o);

    float w = expf((*beta_p) * d);

    if (lane == 0) atomicAdd(&g_denom[t], w);
    atomicAdd(&g_acc[t * HID + lane], w * g_x[s * HID + lane]);
}

// ---------------------------------------------------------------------------
// K3: out = acc/denom; logits = out @ W2^T + b2; log_softmax(2).
// One warp per node.
// ---------------------------------------------------------------------------
__global__ void __launch_bounds__(256) k3_out(
    const float* __restrict__ W2,
    const float* __restrict__ b2,
    float* __restrict__ out)
{
    int lane = threadIdx.x & 31;
    int n = blockIdx.x * (blockDim.x >> 5) + (threadIdx.x >> 5);
    if (n >= N_NODES) return;

    float o = g_acc[n * HID + lane] / g_denom[n];

    float r0 = o * W2[lane];         // W2 row 0
    float r1 = o * W2[HID + lane];   // W2 row 1
    #pragma unroll
    for (int off = 16; off > 0; off >>= 1) {
        r0 += __shfl_xor_sync(0xffffffffu, r0, off);
        r1 += __shfl_xor_sync(0xffffffffu, r1, off);
    }

    if (lane == 0) {
        float l0 = r0 + b2[0];
        float l1 = r1 + b2[1];
        float m  = fmaxf(l0, l1);
        float z  = m + logf(expf(l0 - m) + expf(l1 - m));
        out[n * 2 + 0] = l0 - z;
        out[n * 2 + 1] = l1 - z;
    }
}

// ---------------------------------------------------------------------------
// Launch. Inputs (metadata order):
//   0: X [N,100] f32   1: lin1_w [32,100] f32   2: lin1_b [32] f32
//   3: beta scalar f32 4: lin2_w [2,32]  f32   5: lin2_b [2] f32
//   6: edge_index [2,E] i32 (row 0 = src, row 1 = tgt)
// Output: [N,2] f32 log-probs
// ---------------------------------------------------------------------------
extern "C" void kernel_launch(void* const* d_in, const int* in_sizes, int n_in,
                              void* d_out, int out_size)
{
    const float* X    = (const float*)d_in[0];
    const float* W1   = (const float*)d_in[1];
    const float* b1   = (const float*)d_in[2];
    const float* beta = (const float*)d_in[3];
    const float* W2   = (const float*)d_in[4];
    const float* b2   = (const float*)d_in[5];
    const int*   ei   = (const int*)  d_in[6];
    const int* esrc = ei;
    const int* etgt = ei + N_EDGES;
    float* out = (float*)d_out;

    const int WPB = 256 / 32;  // warps (nodes/edges) per block

    int g1 = (N_NODES + WPB - 1) / WPB;
    k1_lin1_norm<<<g1, 256>>>(X, W1, b1, beta);

    int g2 = (N_EDGES + WPB - 1) / WPB;
    k2_edges<<<g2, 256>>>(esrc, etgt, beta);

    k3_out<<<g1, 256>>>(W2, b2, out);
}

// round 2
// speedup vs baseline: 2.8844x; 2.8844x over previous
#include <cuda_runtime.h>
#include <cuda_bf16.h>
#include <math.h>

#define N_NODES 100000
#define N_FEAT  100
#define HID     32
#define N_EDGES 1600000
#define NCHUNK  25          // N_FEAT/4 float4 chunks per W1 row

// Scratch (static device globals — no allocations allowed)
__device__ float g_xn   [N_NODES * HID];  // row-normalized features
__device__ float g_nrm  [N_NODES];        // row norms (x = xn * nrm)
__device__ float g_acc  [N_NODES * HID];  // unnormalized weighted aggregate
__device__ float g_denom[N_NODES];        // sum of exp(alpha)

// ---------------------------------------------------------------------------
// K1: x = relu(X @ W1^T + b1); xn = x/||x||; init acc/denom with self-loop.
// Register-resident weights: warp w owns k-chunks [3w,3w+3) (warp 7: 4 chunks),
// lane = hid. 8 nodes per block; X staged as float4 in smem, read as
// broadcast LDS.128 (no per-node weight traffic through the crossbar).
// ---------------------------------------------------------------------------
__global__ void __launch_bounds__(256) k1_lin1_norm(
    const float* __restrict__ X,
    const float* __restrict__ W1,
    const float* __restrict__ b1,
    const float* __restrict__ beta_p)
{
    __shared__ float4 sX4[8 * NCHUNK];       // 8 nodes x 25 float4
    __shared__ float  psum[8 * 8 * 33];      // [node][warp][lane] padded to 33

    const int tid  = threadIdx.x;
    const int w    = tid >> 5;               // warp id = k-chunk group
    const int lane = tid & 31;               // hid

    // weight chunks for this thread (W1 rows are 400B = 25 float4, aligned)
    const int base = (w < 7) ? 3 * w : 21;
    const int nch  = (w < 7) ? 3 : 4;
    const float4* W4 = (const float4*)W1;
    float4 wreg[4];
    #pragma unroll
    for (int j = 0; j < 4; j++)
        wreg[j] = (j < nch) ? W4[lane * NCHUNK + base + j]
                            : make_float4(0.f, 0.f, 0.f, 0.f);

    // stage 8 node rows of X (exact: 100000 = 12500*8)
    const int node0 = blockIdx.x * 8;
    const float4* X4 = (const float4*)X;
    if (tid < 8 * NCHUNK) {
        int n = tid / NCHUNK, c = tid % NCHUNK;
        sX4[tid] = X4[(size_t)(node0 + n) * NCHUNK + c];
    }
    __syncthreads();

    // compute partial dot for each of the 8 nodes
    #pragma unroll
    for (int n = 0; n < 8; n++) {
        float p = 0.f;
        #pragma unroll
        for (int j = 0; j < 4; j++) {
            if (j < nch) {
                float4 x = sX4[n * NCHUNK + base + j];   // broadcast
                p = fmaf(x.x, wreg[j].x, p);
                p = fmaf(x.y, wreg[j].y, p);
                p = fmaf(x.z, wreg[j].z, p);
                p = fmaf(x.w, wreg[j].w, p);
            }
        }
        psum[(n * 8 + w) * 33 + lane] = p;
    }
    __syncthreads();

    // phase 2: warp n finalizes node n (lane = hid)
    const int n = w;
    float v = b1[lane];
    #pragma unroll
    for (int ww = 0; ww < 8; ww++)
        v += psum[(n * 8 + ww) * 33 + lane];
    v = fmaxf(v, 0.0f);

    float s = v * v;
    #pragma unroll
    for (int o = 16; o > 0; o >>= 1) s += __shfl_xor_sync(0xffffffffu, s, o);
    float nrm = fmaxf(sqrtf(s), 1e-12f);
    float xn  = v / nrm;

    const int node = node0 + n;
    const int idx  = node * HID + lane;
    g_xn[idx] = xn;

    // self-loop: alpha = beta * <xn,xn> (handles zero rows correctly)
    float d = xn * xn;
    #pragma unroll
    for (int o = 16; o > 0; o >>= 1) d += __shfl_xor_sync(0xffffffffu, d, o);
    float w0 = __expf((*beta_p) * d);

    g_acc[idx] = w0 * v;                 // initializes acc
    if (lane == 0) {
        g_nrm[node]   = nrm;
        g_denom[node] = w0;              // initializes denom
    }
}

// ---------------------------------------------------------------------------
// K2: per-edge attention + scatter. 8 lanes per edge, 4 edges per warp,
// float4 gathers + vectorized RED. x[s] reconstructed as xn[s]*nrm[s]
// (saves one 128B gather per edge).
// ---------------------------------------------------------------------------
__device__ __forceinline__ void red_add_v4(float* p, float4 v) {
    asm volatile("red.global.add.v4.f32 [%0], {%1, %2, %3, %4};"
                 :: "l"(p), "f"(v.x), "f"(v.y), "f"(v.z), "f"(v.w)
                 : "memory");
}

__global__ void __launch_bounds__(256) k2_edges(
    const int* __restrict__ esrc,
    const int* __restrict__ etgt,
    const float* __restrict__ beta_p)
{
    const int lane = threadIdx.x & 31;
    const int g    = lane >> 3;          // edge group within warp (0..3)
    const int sub  = lane & 7;           // float4 slot within edge (0..7)
    const int warp = (blockIdx.x * blockDim.x + threadIdx.x) >> 5;
    const int e    = warp * 4 + g;
    if (e >= N_EDGES) return;

    const int s = esrc[e];               // uniform within 8-lane group
    const int t = etgt[e];

    const float4 xs = *(const float4*)&g_xn[s * HID + sub * 4];
    const float4 xt = *(const float4*)&g_xn[t * HID + sub * 4];

    float d = xs.x * xt.x + xs.y * xt.y + xs.z * xt.z + xs.w * xt.w;
    #pragma unroll
    for (int o = 4; o > 0; o >>= 1) d += __shfl_xor_sync(0xffffffffu, d, o);

    // cosine in [-1,1] * beta: bounded, so no max-shift needed (softmax is
    // shift-invariant and exp never overflows here)
    const float wgt  = __expf((*beta_p) * d);
    const float coef = wgt * g_nrm[s];   // w * ||x_s|| : x[s] = xn[s]*nrm[s]

    red_add_v4(&g_acc[t * HID + sub * 4],
               make_float4(coef * xs.x, coef * xs.y, coef * xs.z, coef * xs.w));
    if (sub == 0) atomicAdd(&g_denom[t], wgt);
}

// ---------------------------------------------------------------------------
// K3: out = acc/denom; logits = out @ W2^T + b2; log_softmax(2).
// One warp per node.
// ---------------------------------------------------------------------------
__global__ void __launch_bounds__(256) k3_out(
    const float* __restrict__ W2,
    const float* __restrict__ b2,
    float* __restrict__ out)
{
    const int lane = threadIdx.x & 31;
    const int n = blockIdx.x * (blockDim.x >> 5) + (threadIdx.x >> 5);
    if (n >= N_NODES) return;

    const float o = g_acc[n * HID + lane] / g_denom[n];

    float r0 = o * W2[lane];             // W2 row 0
    float r1 = o * W2[HID + lane];       // W2 row 1
    #pragma unroll
    for (int off = 16; off > 0; off >>= 1) {
        r0 += __shfl_xor_sync(0xffffffffu, r0, off);
        r1 += __shfl_xor_sync(0xffffffffu, r1, off);
    }

    if (lane == 0) {
        float l0 = r0 + b2[0];
        float l1 = r1 + b2[1];
        float m  = fmaxf(l0, l1);
        float z  = m + logf(expf(l0 - m) + expf(l1 - m));
        out[n * 2 + 0] = l0 - z;
        out[n * 2 + 1] = l1 - z;
    }
}

// ---------------------------------------------------------------------------
// Inputs (metadata order):
//   0: X [N,100] f32   1: lin1_w [32,100] f32   2: lin1_b [32] f32
//   3: beta scalar f32 4: lin2_w [2,32]  f32   5: lin2_b [2] f32
//   6: edge_index [2,E] i32 (row 0 = src, row 1 = tgt)
// Output: [N,2] f32 log-probs
// ---------------------------------------------------------------------------
extern "C" void kernel_launch(void* const* d_in, const int* in_sizes, int n_in,
                              void* d_out, int out_size)
{
    const float* X    = (const float*)d_in[0];
    const float* W1   = (const float*)d_in[1];
    const float* b1   = (const float*)d_in[2];
    const float* beta = (const float*)d_in[3];
    const float* W2   = (const float*)d_in[4];
    const float* b2   = (const float*)d_in[5];
    const int*   ei   = (const int*)  d_in[6];
    const int* esrc = ei;
    const int* etgt = ei + N_EDGES;
    float* out = (float*)d_out;

    // K1: 8 nodes per block, exact division
    k1_lin1_norm<<<N_NODES / 8, 256>>>(X, W1, b1, beta);

    // K2: 32 edges per block (4 per warp)
    k2_edges<<<N_EDGES / 32, 256>>>(esrc, etgt, beta);

    // K3: 8 nodes per block (warp per node)
    k3_out<<<(N_NODES + 7) / 8, 256>>>(W2, b2, out);
}